// round 6
// baseline (speedup 1.0000x reference)
#include <cuda_runtime.h>
#include <cuda_bf16.h>

// ---------------------------------------------------------------------------
// G2EquivariantFeedForward, GB300 sm_103a — round 6
//
// Closed form: upd = a*x + b*x^2 + c*x^3 = (P, Q*v) for x = r + v,
//   P = a*r + b*(r^2-n^2) + c*r*(r^2-3n^2)
//   Q = a + 2*b*r + c*(3r^2-n^2),  n^2=|v|^2,  |upd|^2 = P^2 + Q^2 n^2
//
// Round 6: perfectly coalesced global access via lane-pair shuffle transpose.
//   Thread t touches float4s  base + t + 128k  (4 wf per LDG/STG.128 — was 8
//   with the old 32B-stride layout). Even lane holds low halves, odd lane the
//   high halves of the pair's 8 octonions; butterfly SHFLs exchange the few
//   scalars (partial norms / r in, K / o0 out). MLP loop unchanged: two f32x2
//   streams, 3x LDS.128 broadcast weights/iter, tanh.approx GELU with the
//   0.5 folded into W2.
// ---------------------------------------------------------------------------

typedef unsigned long long U64;

__device__ __forceinline__ U64 pk2(float lo, float hi) {
    U64 r; asm("mov.b64 %0, {%1, %2};" : "=l"(r) : "f"(lo), "f"(hi)); return r;
}
__device__ __forceinline__ void upk2(U64 v, float& lo, float& hi) {
    asm("mov.b64 {%0, %1}, %2;" : "=f"(lo), "=f"(hi) : "l"(v));
}
__device__ __forceinline__ U64 fma2(U64 a, U64 b, U64 c) {
    U64 d; asm("fma.rn.f32x2 %0, %1, %2, %3;" : "=l"(d) : "l"(a), "l"(b), "l"(c)); return d;
}
__device__ __forceinline__ U64 mul2(U64 a, U64 b) {
    U64 d; asm("mul.rn.f32x2 %0, %1, %2;" : "=l"(d) : "l"(a), "l"(b)); return d;
}
__device__ __forceinline__ U64 add2(U64 a, U64 b) {
    U64 d; asm("add.rn.f32x2 %0, %1, %2;" : "=l"(d) : "l"(a), "l"(b)); return d;
}
__device__ __forceinline__ float tanh_ap(float x) {
    float t; asm("tanh.approx.f32 %0, %1;" : "=f"(t) : "f"(x)); return t;
}
__device__ __forceinline__ float sqrt_ap(float x) {
    float t; asm("sqrt.approx.f32 %0, %1;" : "=f"(t) : "f"(x)); return t;
}
__device__ __forceinline__ float rsqrt_ap(float x) {
    float t; asm("rsqrt.approx.f32 %0, %1;" : "=f"(t) : "f"(x)); return t;
}

#define TPB 128          // threads per block
#define F4PB 1024        // float4s per block = 512 octonions

__global__ __launch_bounds__(TPB, 8)
void g2ff_kernel(const float4* __restrict__ in4,
                 const float*  __restrict__ W1,   // (32,2) row-major
                 const float*  __restrict__ b1,   // (32)
                 const float*  __restrict__ W2,   // (3,32) row-major
                 const float*  __restrict__ b2,   // (3)
                 const float*  __restrict__ alpha,
                 float4*       __restrict__ out4)
{
    __shared__ ulonglong2 sW1[32];   // (w0,w0 | w1,w1)
    __shared__ ulonglong2 sBW[32];   // (b1,b1 | 0.5*w2c,0.5*w2c)
    __shared__ ulonglong2 sW2[32];   // (0.5*w2a,.. | 0.5*w2b,..)
    __shared__ U64        sB2[3];
    __shared__ float      sScal[2];

    const int t = threadIdx.x;
    if (t < 32) {
        float w0 = W1[2 * t], w1 = W1[2 * t + 1];
        ulonglong2 q; q.x = pk2(w0, w0); q.y = pk2(w1, w1);
        sW1[t] = q;
        float bb = b1[t], wc = 0.5f * W2[64 + t];
        ulonglong2 qb; qb.x = pk2(bb, bb); qb.y = pk2(wc, wc);
        sBW[t] = qb;
        float wa = 0.5f * W2[t], wb = 0.5f * W2[32 + t];
        ulonglong2 q2; q2.x = pk2(wa, wa); q2.y = pk2(wb, wb);
        sW2[t] = q2;
    } else if (t == 32) {
        float al  = alpha[0];
        float lam = 1.0f / (1.0f + __expf(-al));
        sScal[0] = lam;
        sScal[1] = 1.0f - lam;
        sB2[0] = pk2(b2[0], b2[0]);
        sB2[1] = pk2(b2[1], b2[1]);
        sB2[2] = pk2(b2[2], b2[2]);
    }
    __syncthreads();

    const int fbase = blockIdx.x * F4PB + t;   // thread's float4 stream base
    const int isHi  = t & 1;                   // odd lane: high halves

    // ---- prologue: coalesced loads, per-float4 sum of squares ----
    // even lane: float4 k is the LOW  half (p0..p3) of oct (pair,k); r = .x
    // odd  lane: float4 k is the HIGH half (p4..p7) of the same oct
    float q[8], r[8];
#pragma unroll
    for (int k = 0; k < 8; k++) {
        float4 v = in4[fbase + 128 * k];
        float s = v.x * v.x;
        s = fmaf(v.y, v.y, s);
        s = fmaf(v.z, v.z, s);
        s = fmaf(v.w, v.w, s);
        q[k] = s;
        r[k] = v.x;          // meaningful on even lanes only
    }

    // ---- butterfly exchange: each lane ends up owning 4 complete octonions
    // even lane owns global k=0..3, odd lane owns global k=4..7.
    float rOwn[4], n2Own[4];
#pragma unroll
    for (int j = 0; j < 4; j++) {
        // even sends q[j+4] (odd needs it), odd sends q[j] (even needs it)
        float qsw = __shfl_xor_sync(0xFFFFFFFFu, isHi ? q[j] : q[j + 4], 1);
        // even sends r[j+4] (odd needs it); odd's payload is ignored
        float rsw = __shfl_xor_sync(0xFFFFFFFFu, r[j + 4], 1);
        float rr  = isHi ? rsw : r[j];
        float qOwnHalf = isHi ? q[j + 4] : q[j];
        float n2 = qOwnHalf + qsw - rr * rr;   // (q includes r^2 on the low half)
        n2Own[j] = fmaxf(n2, 0.0f);            // guard sqrt against -eps
        rOwn[j]  = rr;
    }

    // pack two f32x2 streams: X = (oct0, oct1), Y = (oct2, oct3)
    U64 Xp0 = pk2(rOwn[0], rOwn[1]);
    U64 Yp0 = pk2(rOwn[2], rOwn[3]);
    U64 Xnp = pk2(sqrt_ap(n2Own[0]), sqrt_ap(n2Own[1]));
    U64 Ynp = pk2(sqrt_ap(n2Own[2]), sqrt_ap(n2Own[3]));

    // GELU-tanh constants
    const U64 C1 = pk2(0.7978845608028654f, 0.7978845608028654f);
    const U64 C2 = pk2(0.035677408136300125f, 0.035677408136300125f);

    U64 aAX = sB2[0], aBX = sB2[1], aCX = sB2[2];
    U64 aAY = sB2[0], aBY = sB2[1], aCY = sB2[2];

#pragma unroll
    for (int j = 0; j < 32; j++) {
        ulonglong2 w1j = sW1[j];     // LDS.128 broadcast
        ulonglong2 bwj = sBW[j];     // LDS.128 broadcast
        ulonglong2 w2j = sW2[j];     // LDS.128 broadcast

        // stream X:  h' = z*(1+tanh(u)) = 2*gelu(z); W2 tables pre-halved
        {
            U64 z  = fma2(Xnp, w1j.y, fma2(Xp0, w1j.x, bwj.x));
            U64 z2 = mul2(z, z);
            U64 qq = fma2(z2, C2, C1);
            U64 u  = mul2(z, qq);
            float ul, uh; upk2(u, ul, uh);
            U64 tt = pk2(tanh_ap(ul), tanh_ap(uh));
            U64 h  = fma2(z, tt, z);
            aAX = fma2(h, w2j.x, aAX);
            aBX = fma2(h, w2j.y, aBX);
            aCX = fma2(h, bwj.y, aCX);
        }
        // stream Y
        {
            U64 z  = fma2(Ynp, w1j.y, fma2(Yp0, w1j.x, bwj.x));
            U64 z2 = mul2(z, z);
            U64 qq = fma2(z2, C2, C1);
            U64 u  = mul2(z, qq);
            float ul, uh; upk2(u, ul, uh);
            U64 tt = pk2(tanh_ap(ul), tanh_ap(uh));
            U64 h  = fma2(z, tt, z);
            aAY = fma2(h, w2j.x, aAY);
            aBY = fma2(h, w2j.y, aBY);
            aCY = fma2(h, bwj.y, aCY);
        }
    }

    const U64 N1  = pk2(-1.0f, -1.0f);
    const U64 N3  = pk2(-3.0f, -3.0f);
    const U64 TWO = pk2(2.0f, 2.0f);

    const float lam = sScal[0], oml = sScal[1];
    const U64 LAM = pk2(lam, lam);
    const U64 OML = pk2(oml, oml);

    // ---- per-owned-oct coefficients: K (imag scale) and o0 (new scalar) ----
    float Kown[4], o0own[4];
    {
        U64 n2 = mul2(Xnp, Xnp);
        U64 r2 = mul2(Xp0, Xp0);
        U64 s2 = fma2(n2, N1, r2);
        U64 u3 = fma2(n2, N3, r2);
        U64 s3 = mul2(Xp0, u3);
        U64 t3 = fma2(r2, TWO, s2);
        U64 P  = fma2(aAX, Xp0, fma2(aBX, s2, mul2(aCX, s3)));
        U64 tr = add2(Xp0, Xp0);
        U64 Q  = fma2(aCX, t3, fma2(aBX, tr, aAX));
        U64 ss = fma2(mul2(Q, Q), n2, mul2(P, P));
        float sl, sh; upk2(ss, sl, sh);
        sl = fmaxf(sl, 1e-16f);
        sh = fmaxf(sh, 1e-16f);
        U64 inv = pk2(rsqrt_ap(sl), rsqrt_ap(sh));
        U64 li  = mul2(LAM, inv);
        U64 K   = fma2(li, Q, OML);
        U64 o0  = fma2(li, P, mul2(Xp0, OML));
        upk2(K,  Kown[0],  Kown[1]);
        upk2(o0, o0own[0], o0own[1]);
    }
    {
        U64 n2 = mul2(Ynp, Ynp);
        U64 r2 = mul2(Yp0, Yp0);
        U64 s2 = fma2(n2, N1, r2);
        U64 u3 = fma2(n2, N3, r2);
        U64 s3 = mul2(Yp0, u3);
        U64 t3 = fma2(r2, TWO, s2);
        U64 P  = fma2(aAY, Yp0, fma2(aBY, s2, mul2(aCY, s3)));
        U64 tr = add2(Yp0, Yp0);
        U64 Q  = fma2(aCY, t3, fma2(aBY, tr, aAY));
        U64 ss = fma2(mul2(Q, Q), n2, mul2(P, P));
        float sl, sh; upk2(ss, sl, sh);
        sl = fmaxf(sl, 1e-16f);
        sh = fmaxf(sh, 1e-16f);
        U64 inv = pk2(rsqrt_ap(sl), rsqrt_ap(sh));
        U64 li  = mul2(LAM, inv);
        U64 K   = fma2(li, Q, OML);
        U64 o0  = fma2(li, P, mul2(Yp0, OML));
        upk2(K,  Kown[2],  Kown[3]);
        upk2(o0, o0own[2], o0own[3]);
    }

    // ---- butterfly exchange back: assemble K/o0 for all 8 global k ----
    float Kall[8], o0all[8];
#pragma unroll
    for (int j = 0; j < 4; j++) {
        float Ksw  = __shfl_xor_sync(0xFFFFFFFFu, Kown[j], 1);
        float o0sw = __shfl_xor_sync(0xFFFFFFFFu, o0own[j], 1);
        if (isHi) {
            Kall[j]      = Ksw;       // partner owns k=0..3
            Kall[j + 4]  = Kown[j];   // I own k=4..7
            o0all[j]     = o0sw;      // unused on odd lanes, kept for symmetry
            o0all[j + 4] = o0own[j];
        } else {
            Kall[j]      = Kown[j];
            Kall[j + 4]  = Ksw;
            o0all[j]     = o0own[j];
            o0all[j + 4] = o0sw;
        }
    }

    // ---- coalesced re-load (L2 hit), scale, coalesced store ----
#pragma unroll
    for (int k = 0; k < 8; k++) {
        float4 v = in4[fbase + 128 * k];
        float K = Kall[k];
        float x0 = isHi ? v.x * K : o0all[k];   // odd lane: p4 scales; even: new scalar
        v.x = x0;
        v.y *= K; v.z *= K; v.w *= K;
        out4[fbase + 128 * k] = v;
    }
}

extern "C" void kernel_launch(void* const* d_in, const int* in_sizes, int n_in,
                              void* d_out, int out_size)
{
    const float* o     = (const float*)d_in[0];
    const float* W1    = (const float*)d_in[1];
    const float* b1    = (const float*)d_in[2];
    const float* W2    = (const float*)d_in[3];
    const float* b2    = (const float*)d_in[4];
    const float* alpha = (const float*)d_in[5];

    const int total = in_sizes[0];          // 33,554,432 floats
    const int blocks = total / (F4PB * 4);  // 8192 blocks of 1024 float4s

    g2ff_kernel<<<blocks, TPB>>>((const float4*)o, W1, b1, W2, b2, alpha,
                                 (float4*)d_out);
}

// round 7
// speedup vs baseline: 1.4629x; 1.4629x over previous
#include <cuda_runtime.h>
#include <cuda_bf16.h>

// ---------------------------------------------------------------------------
// G2EquivariantFeedForward, GB300 sm_103a — round 7
//
// Closed form: upd = a*x + b*x^2 + c*x^3 = (P, Q*v) for x = r + v,
//   P = a*r + b*(r^2-n^2) + c*r*(r^2-3n^2)
//   Q = a + 2*b*r + c*(3r^2-n^2),  n^2=|v|^2,  |upd|^2 = P^2 + Q^2 n^2
//
// Round 7: coalesced (16B lane stride) global access via lane-pair shuffle
// transpose, restructured from round 6 to keep the live set tiny (round 6
// spilled under the 64-reg clamp and regressed):
//  - phase A computes (r, n^2) per k IMMEDIATELY after each load; the pair's
//    two lanes compute identical values, so no conditional stores;
//  - owned-set selection fused into the second 4-iteration pass;
//  - MLP loop byte-identical to round 5 (known-good);
//  - epilogue exchanges K/o0 with 8 SHFLs, single SEL per k.
// ---------------------------------------------------------------------------

typedef unsigned long long U64;

__device__ __forceinline__ U64 pk2(float lo, float hi) {
    U64 r; asm("mov.b64 %0, {%1, %2};" : "=l"(r) : "f"(lo), "f"(hi)); return r;
}
__device__ __forceinline__ void upk2(U64 v, float& lo, float& hi) {
    asm("mov.b64 {%0, %1}, %2;" : "=f"(lo), "=f"(hi) : "l"(v));
}
__device__ __forceinline__ U64 fma2(U64 a, U64 b, U64 c) {
    U64 d; asm("fma.rn.f32x2 %0, %1, %2, %3;" : "=l"(d) : "l"(a), "l"(b), "l"(c)); return d;
}
__device__ __forceinline__ U64 mul2(U64 a, U64 b) {
    U64 d; asm("mul.rn.f32x2 %0, %1, %2;" : "=l"(d) : "l"(a), "l"(b)); return d;
}
__device__ __forceinline__ U64 add2(U64 a, U64 b) {
    U64 d; asm("add.rn.f32x2 %0, %1, %2;" : "=l"(d) : "l"(a), "l"(b)); return d;
}
__device__ __forceinline__ float tanh_ap(float x) {
    float t; asm("tanh.approx.f32 %0, %1;" : "=f"(t) : "f"(x)); return t;
}
__device__ __forceinline__ float sqrt_ap(float x) {
    float t; asm("sqrt.approx.f32 %0, %1;" : "=f"(t) : "f"(x)); return t;
}
__device__ __forceinline__ float rsqrt_ap(float x) {
    float t; asm("rsqrt.approx.f32 %0, %1;" : "=f"(t) : "f"(x)); return t;
}

#define TPB 128          // threads per block
#define F4PB 1024        // float4s per block = 512 octonions

__global__ __launch_bounds__(TPB, 8)
void g2ff_kernel(const float4* __restrict__ in4,
                 const float*  __restrict__ W1,   // (32,2) row-major
                 const float*  __restrict__ b1,   // (32)
                 const float*  __restrict__ W2,   // (3,32) row-major
                 const float*  __restrict__ b2,   // (3)
                 const float*  __restrict__ alpha,
                 float4*       __restrict__ out4)
{
    __shared__ ulonglong2 sW1[32];   // (w0,w0 | w1,w1)
    __shared__ ulonglong2 sBW[32];   // (b1,b1 | 0.5*w2c,0.5*w2c)
    __shared__ ulonglong2 sW2[32];   // (0.5*w2a,.. | 0.5*w2b,..)
    __shared__ U64        sB2[3];
    __shared__ float      sScal[2];

    const int t = threadIdx.x;
    if (t < 32) {
        float w0 = W1[2 * t], w1 = W1[2 * t + 1];
        ulonglong2 q; q.x = pk2(w0, w0); q.y = pk2(w1, w1);
        sW1[t] = q;
        float bb = b1[t], wc = 0.5f * W2[64 + t];
        ulonglong2 qb; qb.x = pk2(bb, bb); qb.y = pk2(wc, wc);
        sBW[t] = qb;
        float wa = 0.5f * W2[t], wb = 0.5f * W2[32 + t];
        ulonglong2 q2; q2.x = pk2(wa, wa); q2.y = pk2(wb, wb);
        sW2[t] = q2;
    } else if (t == 32) {
        float al  = alpha[0];
        float lam = 1.0f / (1.0f + __expf(-al));
        sScal[0] = lam;
        sScal[1] = 1.0f - lam;
        sB2[0] = pk2(b2[0], b2[0]);
        sB2[1] = pk2(b2[1], b2[1]);
        sB2[2] = pk2(b2[2], b2[2]);
    }
    __syncthreads();

    const int fbase = blockIdx.x * F4PB + t;   // float4 stream base; 16B lane stride
    const bool hi   = (t & 1);                 // odd lane holds high halves

    // ---- phase A: coalesced loads; (r, n2) of the pair's octonion per k ----
    // Pair lanes (2i, 2i+1) share octonion at each k; both compute identical
    // (r, n2). Even lane will MLP octonions k=0..3, odd lane k=4..7.
    float rO0, rO1, rO2, rO3, nO0, nO1, nO2, nO3;
    {
        // pass 1: k = 0..3 (candidate set for even lanes)
        float rT[4], nT[4];
#pragma unroll
        for (int k = 0; k < 4; k++) {
            float4 v = in4[fbase + 128 * k];
            float ss = fmaf(v.w, v.w, fmaf(v.z, v.z, fmaf(v.y, v.y, v.x * v.x)));
            float sw = __shfl_xor_sync(0xFFFFFFFFu, ss, 1);
            float rx = __shfl_xor_sync(0xFFFFFFFFu, v.x, 1);
            float rr = hi ? rx : v.x;
            rT[k] = rr;
            nT[k] = fmaxf(ss + sw - rr * rr, 0.0f);
        }
        // pass 2: k = 4..7; select owned set on the fly (odd keeps these)
#pragma unroll
        for (int k = 0; k < 4; k++) {
            float4 v = in4[fbase + 128 * (k + 4)];
            float ss = fmaf(v.w, v.w, fmaf(v.z, v.z, fmaf(v.y, v.y, v.x * v.x)));
            float sw = __shfl_xor_sync(0xFFFFFFFFu, ss, 1);
            float rx = __shfl_xor_sync(0xFFFFFFFFu, v.x, 1);
            float rr = hi ? rx : v.x;
            float nn = fmaxf(ss + sw - rr * rr, 0.0f);
            rT[k] = hi ? rr : rT[k];
            nT[k] = hi ? nn : nT[k];
        }
        rO0 = rT[0]; rO1 = rT[1]; rO2 = rT[2]; rO3 = rT[3];
        nO0 = nT[0]; nO1 = nT[1]; nO2 = nT[2]; nO3 = nT[3];
    }

    // pack two f32x2 streams: X = (own0, own1), Y = (own2, own3)
    U64 Xp0 = pk2(rO0, rO1);
    U64 Yp0 = pk2(rO2, rO3);
    U64 Xnp = pk2(sqrt_ap(nO0), sqrt_ap(nO1));
    U64 Ynp = pk2(sqrt_ap(nO2), sqrt_ap(nO3));

    // GELU-tanh constants
    const U64 C1 = pk2(0.7978845608028654f, 0.7978845608028654f);
    const U64 C2 = pk2(0.035677408136300125f, 0.035677408136300125f);

    U64 aAX = sB2[0], aBX = sB2[1], aCX = sB2[2];
    U64 aAY = sB2[0], aBY = sB2[1], aCY = sB2[2];

#pragma unroll
    for (int j = 0; j < 32; j++) {
        ulonglong2 w1j = sW1[j];     // LDS.128 broadcast
        ulonglong2 bwj = sBW[j];     // LDS.128 broadcast
        ulonglong2 w2j = sW2[j];     // LDS.128 broadcast

        // stream X:  h' = z*(1+tanh(u)) = 2*gelu(z); W2 tables pre-halved
        {
            U64 z  = fma2(Xnp, w1j.y, fma2(Xp0, w1j.x, bwj.x));
            U64 z2 = mul2(z, z);
            U64 qq = fma2(z2, C2, C1);
            U64 u  = mul2(z, qq);
            float ul, uh; upk2(u, ul, uh);
            U64 tt = pk2(tanh_ap(ul), tanh_ap(uh));
            U64 h  = fma2(z, tt, z);
            aAX = fma2(h, w2j.x, aAX);
            aBX = fma2(h, w2j.y, aBX);
            aCX = fma2(h, bwj.y, aCX);
        }
        // stream Y
        {
            U64 z  = fma2(Ynp, w1j.y, fma2(Yp0, w1j.x, bwj.x));
            U64 z2 = mul2(z, z);
            U64 qq = fma2(z2, C2, C1);
            U64 u  = mul2(z, qq);
            float ul, uh; upk2(u, ul, uh);
            U64 tt = pk2(tanh_ap(ul), tanh_ap(uh));
            U64 h  = fma2(z, tt, z);
            aAY = fma2(h, w2j.x, aAY);
            aBY = fma2(h, w2j.y, aBY);
            aCY = fma2(h, bwj.y, aCY);
        }
    }

    const U64 N1  = pk2(-1.0f, -1.0f);
    const U64 N3  = pk2(-3.0f, -3.0f);
    const U64 TWO = pk2(2.0f, 2.0f);

    const float lam = sScal[0], oml = sScal[1];
    const U64 LAM = pk2(lam, lam);
    const U64 OML = pk2(oml, oml);

    // ---- per-owned-oct coefficients: K (imag scale) and o0 (new scalar) ----
    float Ko[4], Oo[4];
    {
        U64 n2 = mul2(Xnp, Xnp);
        U64 r2 = mul2(Xp0, Xp0);
        U64 s2 = fma2(n2, N1, r2);
        U64 u3 = fma2(n2, N3, r2);
        U64 s3 = mul2(Xp0, u3);
        U64 t3 = fma2(r2, TWO, s2);
        U64 P  = fma2(aAX, Xp0, fma2(aBX, s2, mul2(aCX, s3)));
        U64 tr = add2(Xp0, Xp0);
        U64 Q  = fma2(aCX, t3, fma2(aBX, tr, aAX));
        U64 ss = fma2(mul2(Q, Q), n2, mul2(P, P));
        float sl, sh; upk2(ss, sl, sh);
        sl = fmaxf(sl, 1e-16f);
        sh = fmaxf(sh, 1e-16f);
        U64 inv = pk2(rsqrt_ap(sl), rsqrt_ap(sh));
        U64 li  = mul2(LAM, inv);
        U64 K   = fma2(li, Q, OML);
        U64 o0  = fma2(li, P, mul2(Xp0, OML));
        upk2(K,  Ko[0], Ko[1]);
        upk2(o0, Oo[0], Oo[1]);
    }
    {
        U64 n2 = mul2(Ynp, Ynp);
        U64 r2 = mul2(Yp0, Yp0);
        U64 s2 = fma2(n2, N1, r2);
        U64 u3 = fma2(n2, N3, r2);
        U64 s3 = mul2(Yp0, u3);
        U64 t3 = fma2(r2, TWO, s2);
        U64 P  = fma2(aAY, Yp0, fma2(aBY, s2, mul2(aCY, s3)));
        U64 tr = add2(Yp0, Yp0);
        U64 Q  = fma2(aCY, t3, fma2(aBY, tr, aAY));
        U64 ss = fma2(mul2(Q, Q), n2, mul2(P, P));
        float sl, sh; upk2(ss, sl, sh);
        sl = fmaxf(sl, 1e-16f);
        sh = fmaxf(sh, 1e-16f);
        U64 inv = pk2(rsqrt_ap(sl), rsqrt_ap(sh));
        U64 li  = mul2(LAM, inv);
        U64 K   = fma2(li, Q, OML);
        U64 o0  = fma2(li, P, mul2(Yp0, OML));
        upk2(K,  Ko[2], Ko[3]);
        upk2(o0, Oo[2], Oo[3]);
    }

    // ---- exchange owned coefficients with pair lane (8 SHFLs) ----
    float Kr[4], Or[4];
#pragma unroll
    for (int j = 0; j < 4; j++) {
        Kr[j] = __shfl_xor_sync(0xFFFFFFFFu, Ko[j], 1);
        Or[j] = __shfl_xor_sync(0xFFFFFFFFu, Oo[j], 1);
    }

    // ---- coalesced re-load (L2 hit), scale, coalesced store ----
#pragma unroll
    for (int k = 0; k < 8; k++) {
        // owner of octonion k: even lane if k<4 (slot k), odd lane if k>=4 (slot k-4)
        float Kk = (k < 4) ? (hi ? Kr[k] : Ko[k]) : (hi ? Ko[k - 4] : Kr[k - 4]);
        float Ok = (k < 4) ? Oo[k] : Or[k - 4];   // used by even lanes only
        float4 v = in4[fbase + 128 * k];
        float xs = hi ? v.x * Kk : Ok;            // odd: p4 scales; even: new scalar
        v.x = xs;
        v.y *= Kk; v.z *= Kk; v.w *= Kk;
        out4[fbase + 128 * k] = v;
    }
}

extern "C" void kernel_launch(void* const* d_in, const int* in_sizes, int n_in,
                              void* d_out, int out_size)
{
    const float* o     = (const float*)d_in[0];
    const float* W1    = (const float*)d_in[1];
    const float* b1    = (const float*)d_in[2];
    const float* W2    = (const float*)d_in[3];
    const float* b2    = (const float*)d_in[4];
    const float* alpha = (const float*)d_in[5];

    const int total = in_sizes[0];          // 33,554,432 floats
    const int blocks = total / (F4PB * 4);  // 8192 blocks of 1024 float4s

    g2ff_kernel<<<blocks, TPB>>>((const float4*)o, W1, b1, W2, b2, alpha,
                                 (float4*)d_out);
}

// round 8
// speedup vs baseline: 1.6597x; 1.1345x over previous
#include <cuda_runtime.h>
#include <cuda_bf16.h>

// ---------------------------------------------------------------------------
// G2EquivariantFeedForward, GB300 sm_103a — round 8
//
// Closed form: upd = a*x + b*x^2 + c*x^3 = (P, Q*v) for x = r + v,
//   P = a*r + b*(r^2-n^2) + c*r*(r^2-3n^2)
//   Q = a + 2*b*r + c*(3r^2-n^2),  n^2=|v|^2,  |upd|^2 = P^2 + Q^2 n^2
//
// Round 8 = round 5 compute (best so far, 63.0us) with the weight tables
// moved from shared memory to __constant__:
//   prep kernel packs splat-pair tables into __device__ scratch ->
//   cudaMemcpyToSymbolAsync (D2D, graph-capturable) -> main kernel reads
//   via the constant port (LDC/LDCU), freeing the L1tex/shared crossbar
//   of 96 LDS wavefronts per warp. No smem, no __syncthreads in main kernel.
// ---------------------------------------------------------------------------

typedef unsigned long long U64;

__device__ __forceinline__ U64 pk2(float lo, float hi) {
    U64 r; asm("mov.b64 %0, {%1, %2};" : "=l"(r) : "f"(lo), "f"(hi)); return r;
}
__device__ __forceinline__ void upk2(U64 v, float& lo, float& hi) {
    asm("mov.b64 {%0, %1}, %2;" : "=f"(lo), "=f"(hi) : "l"(v));
}
__device__ __forceinline__ U64 fma2(U64 a, U64 b, U64 c) {
    U64 d; asm("fma.rn.f32x2 %0, %1, %2, %3;" : "=l"(d) : "l"(a), "l"(b), "l"(c)); return d;
}
__device__ __forceinline__ U64 mul2(U64 a, U64 b) {
    U64 d; asm("mul.rn.f32x2 %0, %1, %2;" : "=l"(d) : "l"(a), "l"(b)); return d;
}
__device__ __forceinline__ U64 add2(U64 a, U64 b) {
    U64 d; asm("add.rn.f32x2 %0, %1, %2;" : "=l"(d) : "l"(a), "l"(b)); return d;
}
__device__ __forceinline__ float tanh_ap(float x) {
    float t; asm("tanh.approx.f32 %0, %1;" : "=f"(t) : "f"(x)); return t;
}
__device__ __forceinline__ float sqrt_ap(float x) {
    float t; asm("sqrt.approx.f32 %0, %1;" : "=f"(t) : "f"(x)); return t;
}
__device__ __forceinline__ float rsqrt_ap(float x) {
    float t; asm("rsqrt.approx.f32 %0, %1;" : "=f"(t) : "f"(x)); return t;
}

__device__ __forceinline__ float norm2_imag(const float4& a0, const float4& a1) {
    float n = a0.y * a0.y;
    n = fmaf(a0.z, a0.z, n);
    n = fmaf(a0.w, a0.w, n);
    n = fmaf(a1.x, a1.x, n);
    n = fmaf(a1.y, a1.y, n);
    n = fmaf(a1.z, a1.z, n);
    n = fmaf(a1.w, a1.w, n);
    return n;
}

// ---- packed weight tables: built on device, then copied into __constant__ ----
struct __align__(16) CTab {
    ulonglong2 W1[32];   // (w0,w0 | w1,w1)
    ulonglong2 BW[32];   // (b1,b1 | 0.5*w2c,0.5*w2c)
    ulonglong2 W2[32];   // (0.5*w2a,.. | 0.5*w2b,..)
    U64        B2[3];    // (b2k, b2k)
    float      scal[2];  // lam, 1-lam
};

__device__   CTab dScratch;   // written by prep kernel
__constant__ CTab cT;         // read by main kernel (constant port)

__global__ void prep_kernel(const float* __restrict__ W1,
                            const float* __restrict__ b1,
                            const float* __restrict__ W2,
                            const float* __restrict__ b2,
                            const float* __restrict__ alpha)
{
    const int t = threadIdx.x;     // 32 threads
    float w0 = W1[2 * t], w1 = W1[2 * t + 1];
    ulonglong2 q; q.x = pk2(w0, w0); q.y = pk2(w1, w1);
    dScratch.W1[t] = q;
    float bb = b1[t], wc = 0.5f * W2[64 + t];
    ulonglong2 qb; qb.x = pk2(bb, bb); qb.y = pk2(wc, wc);
    dScratch.BW[t] = qb;
    float wa = 0.5f * W2[t], wb = 0.5f * W2[32 + t];
    ulonglong2 q2; q2.x = pk2(wa, wa); q2.y = pk2(wb, wb);
    dScratch.W2[t] = q2;
    if (t == 0) {
        float al  = alpha[0];
        float lam = 1.0f / (1.0f + __expf(-al));
        dScratch.scal[0] = lam;
        dScratch.scal[1] = 1.0f - lam;
        dScratch.B2[0] = pk2(b2[0], b2[0]);
        dScratch.B2[1] = pk2(b2[1], b2[1]);
        dScratch.B2[2] = pk2(b2[2], b2[2]);
    }
}

#define TPB 128          // threads per block
#define OPB 512          // octonions per block (4 per thread)

__global__ __launch_bounds__(TPB, 8)
void g2ff_kernel(const float4* __restrict__ in4,
                 float4*       __restrict__ out4)
{
    const int t = threadIdx.x;
    const int base = blockIdx.x * OPB;
    const int mA = base + t;
    const int mB = base + TPB + t;
    const int mC = base + 2 * TPB + t;
    const int mD = base + 3 * TPB + t;

    // ---- prologue: scalar n^2 per octonion; pack only (r, np) pairs ----
    U64 Xp0, Xnp, Yp0, Ynp;
    {
        float4 a0 = in4[2 * mA + 0];
        float4 a1 = in4[2 * mA + 1];
        float4 b0 = in4[2 * mB + 0];
        float4 b1v = in4[2 * mB + 1];
        float nA = norm2_imag(a0, a1);
        float nB = norm2_imag(b0, b1v);
        Xp0 = pk2(a0.x, b0.x);
        Xnp = pk2(sqrt_ap(nA), sqrt_ap(nB));
    }
    {
        float4 a0 = in4[2 * mC + 0];
        float4 a1 = in4[2 * mC + 1];
        float4 b0 = in4[2 * mD + 0];
        float4 b1v = in4[2 * mD + 1];
        float nA = norm2_imag(a0, a1);
        float nB = norm2_imag(b0, b1v);
        Yp0 = pk2(a0.x, b0.x);
        Ynp = pk2(sqrt_ap(nA), sqrt_ap(nB));
    }

    // GELU-tanh constants
    const U64 C1 = pk2(0.7978845608028654f, 0.7978845608028654f);
    const U64 C2 = pk2(0.035677408136300125f, 0.035677408136300125f);

    U64 aAX = cT.B2[0], aBX = cT.B2[1], aCX = cT.B2[2];
    U64 aAY = cT.B2[0], aBY = cT.B2[1], aCY = cT.B2[2];

#pragma unroll
    for (int j = 0; j < 32; j++) {
        ulonglong2 w1j = cT.W1[j];   // LDC.128 (constant port, off L1tex)
        ulonglong2 bwj = cT.BW[j];
        ulonglong2 w2j = cT.W2[j];

        // stream X:  h' = z*(1+tanh(u)) = 2*gelu(z); W2 tables pre-halved
        {
            U64 z  = fma2(Xnp, w1j.y, fma2(Xp0, w1j.x, bwj.x));
            U64 z2 = mul2(z, z);
            U64 qq = fma2(z2, C2, C1);
            U64 u  = mul2(z, qq);
            float ul, uh; upk2(u, ul, uh);
            U64 tt = pk2(tanh_ap(ul), tanh_ap(uh));
            U64 h  = fma2(z, tt, z);
            aAX = fma2(h, w2j.x, aAX);
            aBX = fma2(h, w2j.y, aBX);
            aCX = fma2(h, bwj.y, aCX);
        }
        // stream Y
        {
            U64 z  = fma2(Ynp, w1j.y, fma2(Yp0, w1j.x, bwj.x));
            U64 z2 = mul2(z, z);
            U64 qq = fma2(z2, C2, C1);
            U64 u  = mul2(z, qq);
            float ul, uh; upk2(u, ul, uh);
            U64 tt = pk2(tanh_ap(ul), tanh_ap(uh));
            U64 h  = fma2(z, tt, z);
            aAY = fma2(h, w2j.x, aAY);
            aBY = fma2(h, w2j.y, aBY);
            aCY = fma2(h, bwj.y, aCY);
        }
    }

    const U64 N1  = pk2(-1.0f, -1.0f);
    const U64 N3  = pk2(-3.0f, -3.0f);
    const U64 TWO = pk2(2.0f, 2.0f);

    const float lam = cT.scal[0], oml = cT.scal[1];
    const U64 LAM = pk2(lam, lam);
    const U64 OML = pk2(oml, oml);

    // ---- epilogue stream X (re-load octonions from global; L2 hit) ----
    {
        U64 n2 = mul2(Xnp, Xnp);              // recompute (np = sqrt(n2))
        U64 r2 = mul2(Xp0, Xp0);
        U64 s2 = fma2(n2, N1, r2);            // r^2 - n^2
        U64 u3 = fma2(n2, N3, r2);            // r^2 - 3n^2
        U64 s3 = mul2(Xp0, u3);
        U64 t3 = fma2(r2, TWO, s2);           // 3r^2 - n^2
        U64 P  = fma2(aAX, Xp0, fma2(aBX, s2, mul2(aCX, s3)));
        U64 tr = add2(Xp0, Xp0);
        U64 Q  = fma2(aCX, t3, fma2(aBX, tr, aAX));
        U64 ss = fma2(mul2(Q, Q), n2, mul2(P, P));
        float sl, sh; upk2(ss, sl, sh);
        sl = fmaxf(sl, 1e-16f);
        sh = fmaxf(sh, 1e-16f);
        U64 inv = pk2(rsqrt_ap(sl), rsqrt_ap(sh));
        U64 li  = mul2(LAM, inv);
        U64 K   = fma2(li, Q, OML);
        U64 o0  = fma2(li, P, mul2(Xp0, OML));

        float Klo, Khi; upk2(K, Klo, Khi);
        float olo, ohi; upk2(o0, olo, ohi);

        float4 a0 = in4[2 * mA + 0];
        float4 a1 = in4[2 * mA + 1];
        a0.x = olo;
        a0.y *= Klo; a0.z *= Klo; a0.w *= Klo;
        a1.x *= Klo; a1.y *= Klo; a1.z *= Klo; a1.w *= Klo;
        out4[2 * mA + 0] = a0;
        out4[2 * mA + 1] = a1;

        float4 b0 = in4[2 * mB + 0];
        float4 b1v = in4[2 * mB + 1];
        b0.x = ohi;
        b0.y *= Khi; b0.z *= Khi; b0.w *= Khi;
        b1v.x *= Khi; b1v.y *= Khi; b1v.z *= Khi; b1v.w *= Khi;
        out4[2 * mB + 0] = b0;
        out4[2 * mB + 1] = b1v;
    }
    // ---- epilogue stream Y ----
    {
        U64 n2 = mul2(Ynp, Ynp);
        U64 r2 = mul2(Yp0, Yp0);
        U64 s2 = fma2(n2, N1, r2);
        U64 u3 = fma2(n2, N3, r2);
        U64 s3 = mul2(Yp0, u3);
        U64 t3 = fma2(r2, TWO, s2);
        U64 P  = fma2(aAY, Yp0, fma2(aBY, s2, mul2(aCY, s3)));
        U64 tr = add2(Yp0, Yp0);
        U64 Q  = fma2(aCY, t3, fma2(aBY, tr, aAY));
        U64 ss = fma2(mul2(Q, Q), n2, mul2(P, P));
        float sl, sh; upk2(ss, sl, sh);
        sl = fmaxf(sl, 1e-16f);
        sh = fmaxf(sh, 1e-16f);
        U64 inv = pk2(rsqrt_ap(sl), rsqrt_ap(sh));
        U64 li  = mul2(LAM, inv);
        U64 K   = fma2(li, Q, OML);
        U64 o0  = fma2(li, P, mul2(Yp0, OML));

        float Klo, Khi; upk2(K, Klo, Khi);
        float olo, ohi; upk2(o0, olo, ohi);

        float4 a0 = in4[2 * mC + 0];
        float4 a1 = in4[2 * mC + 1];
        a0.x = olo;
        a0.y *= Klo; a0.z *= Klo; a0.w *= Klo;
        a1.x *= Klo; a1.y *= Klo; a1.z *= Klo; a1.w *= Klo;
        out4[2 * mC + 0] = a0;
        out4[2 * mC + 1] = a1;

        float4 b0 = in4[2 * mD + 0];
        float4 b1v = in4[2 * mD + 1];
        b0.x = ohi;
        b0.y *= Khi; b0.z *= Khi; b0.w *= Khi;
        b1v.x *= Khi; b1v.y *= Khi; b1v.z *= Khi; b1v.w *= Khi;
        out4[2 * mD + 0] = b0;
        out4[2 * mD + 1] = b1v;
    }
}

extern "C" void kernel_launch(void* const* d_in, const int* in_sizes, int n_in,
                              void* d_out, int out_size)
{
    const float* o     = (const float*)d_in[0];
    const float* W1    = (const float*)d_in[1];
    const float* b1    = (const float*)d_in[2];
    const float* W2    = (const float*)d_in[3];
    const float* b2    = (const float*)d_in[4];
    const float* alpha = (const float*)d_in[5];

    // 1) pack weight tables on device
    prep_kernel<<<1, 32>>>(W1, b1, W2, b2, alpha);

    // 2) copy packed tables into __constant__ (D2D memcpy node, capturable)
    void* scratch_addr = nullptr;
    cudaGetSymbolAddress(&scratch_addr, dScratch);
    cudaMemcpyToSymbolAsync(cT, scratch_addr, sizeof(CTab), 0,
                            cudaMemcpyDeviceToDevice);

    // 3) main kernel
    const int total = in_sizes[0];          // 33,554,432 floats
    const int octs  = total / 8;            // 4,194,304 octonions
    const int blocks = octs / OPB;          // 8192

    g2ff_kernel<<<blocks, TPB>>>((const float4*)o, (float4*)d_out);
}